// round 2
// baseline (speedup 1.0000x reference)
#include <cuda_runtime.h>
#include <math.h>

#define NNODE 20000
#define EEDGE 320000
#define CC 64
#define NBAS 8
#define NEL 4
#define GG 16
#define NL 9
#define HIDN 16
#define RMAXF 5.0f
#define PI_F 3.14159265358979f

// ---------------- device scratch (no allocation allowed) ----------------
__device__ float d_hu0[NNODE * CC];
__device__ float d_Y[EEDGE * NL];
__device__ float d_ef[EEDGE * NBAS];
__device__ float d_u3[EEDGE * 3];
__device__ float d_r[EEDGE];
__device__ float d_R0[EEDGE * CC];
__device__ float d_R1[EEDGE * CC];
__device__ float d_s1[EEDGE * CC];
__device__ float d_agg0[NNODE * NL * CC];
__device__ float d_hu1[NNODE * NL * CC];
__device__ float d_agg1[NNODE * CC];
__device__ float d_gagg1[NNODE * CC];
__device__ float d_ghu1[NNODE * NL * CC];
__device__ float d_gagg0[NNODE * NL * CC];
__device__ float d_contrib[GG * 3];

// ---------------- K0: zero accumulators ----------------
__global__ void k_zero(float* __restrict__ out, int out_size) {
    int idx = blockIdx.x * blockDim.x + threadIdx.x;
    int total = NNODE * NL * CC;
    if (idx < total) { d_agg0[idx] = 0.f; d_ghu1[idx] = 0.f; }
    if (idx < NNODE * CC) d_agg1[idx] = 0.f;
    if (idx < out_size) out[idx] = 0.f;
    if (idx < GG * 3) d_contrib[idx] = 0.f;
}

// ---------------- K1: node init: h0, hu0, e0 ----------------
__global__ void k_node_init(const float* __restrict__ attrs, const float* __restrict__ ae,
                            const float* __restrict__ W_embed, const float* __restrict__ W_up0,
                            const int* __restrict__ batch) {
    __shared__ float sW[CC * CC];
    __shared__ float sh0[8][CC];
    for (int i = threadIdx.x; i < CC * CC; i += blockDim.x) sW[i] = W_up0[i];
    __syncthreads();
    int warp = threadIdx.x >> 5, lane = threadIdx.x & 31;
    int n = blockIdx.x * 8 + warp;
    if (n >= NNODE) return;
    float a0 = attrs[n * 4 + 0], a1 = attrs[n * 4 + 1], a2 = attrs[n * 4 + 2], a3 = attrs[n * 4 + 3];
    #pragma unroll
    for (int k = 0; k < 2; k++) {
        int c = lane + 32 * k;
        sh0[warp][c] = a0 * W_embed[0 * CC + c] + a1 * W_embed[1 * CC + c]
                     + a2 * W_embed[2 * CC + c] + a3 * W_embed[3 * CC + c];
    }
    __syncwarp();
    #pragma unroll
    for (int k = 0; k < 2; k++) {
        int d = lane + 32 * k;
        float acc = 0.f;
        #pragma unroll 8
        for (int c = 0; c < CC; c++) acc += sh0[warp][c] * sW[c * CC + d];
        d_hu0[n * CC + d] = acc;
    }
    if (lane == 0) {
        float e0 = a0 * ae[0] + a1 * ae[1] + a2 * ae[2] + a3 * ae[3];
        atomicAdd(&d_contrib[batch[n] * 3 + 0], e0);
    }
}

// ---------------- K2: edge geometry + radial MLPs R0, R1 ----------------
__global__ void k_edge_geom(const float* __restrict__ pos, const float* __restrict__ shifts,
                            const int* __restrict__ eidx,
                            const float* __restrict__ W1, const float* __restrict__ W2) {
    __shared__ float sW1[2 * NBAS * CC];
    __shared__ float sW2[2 * CC * CC];
    __shared__ float sact[8][CC];
    for (int i = threadIdx.x; i < 2 * NBAS * CC; i += blockDim.x) sW1[i] = W1[i];
    for (int i = threadIdx.x; i < 2 * CC * CC; i += blockDim.x) sW2[i] = W2[i];
    __syncthreads();
    int warp = threadIdx.x >> 5, lane = threadIdx.x & 31;
    int e = blockIdx.x * 8 + warp;
    if (e >= EEDGE) return;
    int snd = eidx[e], rcv = eidx[EEDGE + e];
    float vx = pos[snd * 3 + 0] - pos[rcv * 3 + 0] + shifts[e * 3 + 0];
    float vy = pos[snd * 3 + 1] - pos[rcv * 3 + 1] + shifts[e * 3 + 1];
    float vz = pos[snd * 3 + 2] - pos[rcv * 3 + 2] + shifts[e * 3 + 2];
    float r = sqrtf(vx * vx + vy * vy + vz * vz + 1e-12f);
    float inv = 1.0f / r;
    float x = vx * inv, y = vy * inv, z = vz * inv;
    const float S3 = 1.7320508075688772f, S5 = 2.23606797749979f, S15 = 3.872983346207417f;
    float Yv[9];
    Yv[0] = 1.f; Yv[1] = S3 * x; Yv[2] = S3 * y; Yv[3] = S3 * z;
    Yv[4] = S15 * x * y; Yv[5] = S15 * y * z; Yv[6] = 0.5f * S5 * (3.f * z * z - 1.f);
    Yv[7] = S15 * x * z; Yv[8] = 0.5f * S15 * (x * x - y * y);
    float uu = r * (1.0f / RMAXF);
    float fc = 0.f;
    if (uu < 1.f) {
        float u2 = uu * uu, u4 = u2 * u2, u6 = u4 * u2, u7 = u6 * uu, u8 = u7 * uu;
        fc = 1.f - 28.f * u6 + 48.f * u7 - 21.f * u8;
    }
    const float A = 0.6324555320336759f;  // sqrt(2/5)
    float ef[NBAS];
    #pragma unroll
    for (int n = 0; n < NBAS; n++) {
        float kn = (n + 1) * (PI_F / RMAXF);
        ef[n] = A * sinf(kn * r) * inv * fc;
    }
    if (lane < 9) d_Y[e * NL + lane] = Yv[lane];
    if (lane < 8) d_ef[e * NBAS + lane] = ef[lane];
    if (lane < 3) d_u3[e * 3 + lane] = (lane == 0 ? x : (lane == 1 ? y : z));
    if (lane == 0) d_r[e] = r;
    #pragma unroll
    for (int i = 0; i < 2; i++) {
        const float* w1 = &sW1[i * NBAS * CC];
        const float* w2 = &sW2[i * CC * CC];
        #pragma unroll
        for (int k = 0; k < 2; k++) {
            int j = lane + 32 * k;
            float zv = 0.f;
            #pragma unroll
            for (int n = 0; n < NBAS; n++) zv += ef[n] * w1[n * CC + j];
            float sg = 1.f / (1.f + __expf(-zv));
            sact[warp][j] = zv * sg;
        }
        __syncwarp();
        float* Rdst = i ? d_R1 : d_R0;
        #pragma unroll
        for (int k = 0; k < 2; k++) {
            int c = lane + 32 * k;
            float acc = 0.f;
            #pragma unroll 8
            for (int j = 0; j < CC; j++) acc += sact[warp][j] * w2[j * CC + c];
            Rdst[e * CC + c] = acc;
        }
        __syncwarp();
    }
}

// ---------------- K3: forward scatter m0 -> agg0 ----------------
__global__ void k_msg0(const int* __restrict__ eidx) {
    int warp = threadIdx.x >> 5, lane = threadIdx.x & 31;
    int e = blockIdx.x * 8 + warp;
    if (e >= EEDGE) return;
    int snd = eidx[e], rcv = eidx[EEDGE + e];
    float Yv[9];
    #pragma unroll
    for (int l = 0; l < 9; l++) Yv[l] = d_Y[e * NL + l];
    #pragma unroll
    for (int k = 0; k < 2; k++) {
        int c = lane + 32 * k;
        float p = d_R0[e * CC + c] * d_hu0[snd * CC + c];
        float* base = &d_agg0[(rcv * NL) * CC + c];
        #pragma unroll
        for (int l = 0; l < 9; l++) atomicAdd(base + l * CC, Yv[l] * p);
    }
}

// ---------------- K4: node update: h1 = agg0@Wout0 (+skip), en0, hu1 = h1@Wup1 ----------------
__global__ void k_node_upd(const float* __restrict__ attrs, const float* __restrict__ W_out0,
                           const float* __restrict__ W_skip0, const float* __restrict__ w_read0,
                           const float* __restrict__ W_up1, const int* __restrict__ batch) {
    __shared__ float sWo[CC * CC];
    __shared__ float sWu[CC * CC];
    __shared__ float sSk[NEL * CC];
    __shared__ float srd[CC];
    __shared__ float scr[8][CC];
    for (int i = threadIdx.x; i < CC * CC; i += blockDim.x) { sWo[i] = W_out0[i]; sWu[i] = W_up1[i]; }
    for (int i = threadIdx.x; i < NEL * CC; i += blockDim.x) sSk[i] = W_skip0[i];
    for (int i = threadIdx.x; i < CC; i += blockDim.x) srd[i] = w_read0[i];
    __syncthreads();
    int warp = threadIdx.x >> 5, lane = threadIdx.x & 31;
    int idx = blockIdx.x * 8 + warp;
    if (idx >= NNODE * NL) return;
    int n = idx / NL, l = idx - n * NL;
    int row = idx * CC;
    scr[warp][lane] = d_agg0[row + lane];
    scr[warp][lane + 32] = d_agg0[row + lane + 32];
    __syncwarp();
    float h1v[2];
    float a0 = 0, a1 = 0, a2 = 0, a3 = 0;
    if (l == 0) { a0 = attrs[n * 4 + 0]; a1 = attrs[n * 4 + 1]; a2 = attrs[n * 4 + 2]; a3 = attrs[n * 4 + 3]; }
    #pragma unroll
    for (int k = 0; k < 2; k++) {
        int d = lane + 32 * k;
        float acc = 0.f;
        #pragma unroll 8
        for (int c = 0; c < CC; c++) acc += scr[warp][c] * sWo[c * CC + d];
        if (l == 0) acc += a0 * sSk[d] + a1 * sSk[CC + d] + a2 * sSk[2 * CC + d] + a3 * sSk[3 * CC + d];
        h1v[k] = acc;
    }
    if (l == 0) {
        float ep = h1v[0] * srd[lane] + h1v[1] * srd[lane + 32];
        #pragma unroll
        for (int off = 16; off > 0; off >>= 1) ep += __shfl_xor_sync(0xffffffff, ep, off);
        if (lane == 0) atomicAdd(&d_contrib[batch[n] * 3 + 1], ep);
    }
    __syncwarp();
    scr[warp][lane] = h1v[0]; scr[warp][lane + 32] = h1v[1];
    __syncwarp();
    #pragma unroll
    for (int k = 0; k < 2; k++) {
        int d = lane + 32 * k;
        float acc = 0.f;
        #pragma unroll 8
        for (int c = 0; c < CC; c++) acc += scr[warp][c] * sWu[c * CC + d];
        d_hu1[row + d] = acc;
    }
}

// ---------------- K5: forward edge iter1: s1, scatter to agg1 (l=0 only) ----------------
__global__ void k_msg1(const int* __restrict__ eidx) {
    int warp = threadIdx.x >> 5, lane = threadIdx.x & 31;
    int e = blockIdx.x * 8 + warp;
    if (e >= EEDGE) return;
    int snd = eidx[e], rcv = eidx[EEDGE + e];
    float Yv[9];
    #pragma unroll
    for (int l = 0; l < 9; l++) Yv[l] = d_Y[e * NL + l];
    #pragma unroll
    for (int k = 0; k < 2; k++) {
        int c = lane + 32 * k;
        float s = 0.f;
        #pragma unroll
        for (int l = 0; l < 9; l++) s += d_hu1[(snd * NL + l) * CC + c] * Yv[l];
        d_s1[e * CC + c] = s;
        atomicAdd(&d_agg1[rcv * CC + c], d_R1[e * CC + c] * s);
    }
}

// ---------------- K6: node2: h2_0, en1, backward head -> g_agg1 ----------------
__global__ void k_node2(const float* __restrict__ attrs, const float* __restrict__ W_out1,
                        const float* __restrict__ W_skip1, const float* __restrict__ W_r1,
                        const float* __restrict__ w_r2, const int* __restrict__ batch) {
    __shared__ float sWo[CC * CC];
    __shared__ float sWoT[CC * CC];
    __shared__ float sWr[CC * 17];
    __shared__ float sr2[HIDN];
    __shared__ float sSk[NEL * CC];
    __shared__ float scr[8][CC];
    __shared__ float sgz[8][HIDN];
    for (int i = threadIdx.x; i < CC * CC; i += blockDim.x) {
        sWo[i] = W_out1[i];
        int d = i / CC, c = i % CC;
        sWoT[i] = W_out1[c * CC + d];
    }
    for (int i = threadIdx.x; i < CC * HIDN; i += blockDim.x) {
        int c = i / HIDN, h = i % HIDN;
        sWr[c * 17 + h] = W_r1[i];
    }
    for (int i = threadIdx.x; i < HIDN; i += blockDim.x) sr2[i] = w_r2[i];
    for (int i = threadIdx.x; i < NEL * CC; i += blockDim.x) sSk[i] = W_skip1[i];
    __syncthreads();
    int warp = threadIdx.x >> 5, lane = threadIdx.x & 31;
    int n = blockIdx.x * 8 + warp;
    if (n >= NNODE) return;
    scr[warp][lane] = d_agg1[n * CC + lane];
    scr[warp][lane + 32] = d_agg1[n * CC + lane + 32];
    __syncwarp();
    float a0 = attrs[n * 4 + 0], a1 = attrs[n * 4 + 1], a2 = attrs[n * 4 + 2], a3 = attrs[n * 4 + 3];
    float h2[2];
    #pragma unroll
    for (int k = 0; k < 2; k++) {
        int d = lane + 32 * k;
        float acc = a0 * sSk[d] + a1 * sSk[CC + d] + a2 * sSk[2 * CC + d] + a3 * sSk[3 * CC + d];
        #pragma unroll 8
        for (int c = 0; c < CC; c++) acc += scr[warp][c] * sWo[c * CC + d];
        h2[k] = acc;
    }
    __syncwarp();
    scr[warp][lane] = h2[0]; scr[warp][lane + 32] = h2[1];
    __syncwarp();
    float ep = 0.f;
    if (lane < HIDN) {
        float zv = 0.f;
        #pragma unroll 8
        for (int d = 0; d < CC; d++) zv += scr[warp][d] * sWr[d * 17 + lane];
        float sg = 1.f / (1.f + __expf(-zv));
        ep = zv * sg * sr2[lane];
        sgz[warp][lane] = sg * (1.f + zv * (1.f - sg)) * sr2[lane];
    }
    #pragma unroll
    for (int off = 16; off > 0; off >>= 1) ep += __shfl_xor_sync(0xffffffff, ep, off);
    if (lane == 0) atomicAdd(&d_contrib[batch[n] * 3 + 2], ep);
    __syncwarp();
    float gh2[2];
    #pragma unroll
    for (int k = 0; k < 2; k++) {
        int d = lane + 32 * k;
        float acc = 0.f;
        #pragma unroll
        for (int h = 0; h < HIDN; h++) acc += sgz[warp][h] * sWr[d * 17 + h];
        gh2[k] = acc;
    }
    __syncwarp();
    scr[warp][lane] = gh2[0]; scr[warp][lane + 32] = gh2[1];
    __syncwarp();
    #pragma unroll
    for (int k = 0; k < 2; k++) {
        int c = lane + 32 * k;
        float acc = 0.f;
        #pragma unroll 8
        for (int d = 0; d < CC; d++) acc += scr[warp][d] * sWoT[d * CC + c];
        d_gagg1[n * CC + c] = acc;
    }
}

// ---------------- K7: backward scatter g_hu1 ----------------
__global__ void k_back_scatter(const int* __restrict__ eidx) {
    int warp = threadIdx.x >> 5, lane = threadIdx.x & 31;
    int e = blockIdx.x * 8 + warp;
    if (e >= EEDGE) return;
    int snd = eidx[e], rcv = eidx[EEDGE + e];
    float Yv[9];
    #pragma unroll
    for (int l = 0; l < 9; l++) Yv[l] = d_Y[e * NL + l];
    #pragma unroll
    for (int k = 0; k < 2; k++) {
        int c = lane + 32 * k;
        float gs1 = d_R1[e * CC + c] * d_gagg1[rcv * CC + c];
        float* base = &d_ghu1[(snd * NL) * CC + c];
        #pragma unroll
        for (int l = 0; l < 9; l++) atomicAdd(base + l * CC, Yv[l] * gs1);
    }
}

// ---------------- K8: backward node: g_h1 -> g_agg0 ----------------
__global__ void k_back_node(const float* __restrict__ W_up1, const float* __restrict__ W_out0,
                            const float* __restrict__ w_read0) {
    __shared__ float sWuT[CC * CC];
    __shared__ float sWoT[CC * CC];
    __shared__ float srd[CC];
    __shared__ float scr[8][CC];
    for (int i = threadIdx.x; i < CC * CC; i += blockDim.x) {
        int d = i / CC, c = i % CC;
        sWuT[i] = W_up1[c * CC + d];
        sWoT[i] = W_out0[c * CC + d];
    }
    for (int i = threadIdx.x; i < CC; i += blockDim.x) srd[i] = w_read0[i];
    __syncthreads();
    int warp = threadIdx.x >> 5, lane = threadIdx.x & 31;
    int idx = blockIdx.x * 8 + warp;
    if (idx >= NNODE * NL) return;
    int l = idx % NL;
    int row = idx * CC;
    scr[warp][lane] = d_ghu1[row + lane];
    scr[warp][lane + 32] = d_ghu1[row + lane + 32];
    __syncwarp();
    float gh1[2];
    #pragma unroll
    for (int k = 0; k < 2; k++) {
        int c = lane + 32 * k;
        float acc = 0.f;
        #pragma unroll 8
        for (int d = 0; d < CC; d++) acc += scr[warp][d] * sWuT[d * CC + c];
        if (l == 0) acc += srd[c];
        gh1[k] = acc;
    }
    __syncwarp();
    scr[warp][lane] = gh1[0]; scr[warp][lane + 32] = gh1[1];
    __syncwarp();
    #pragma unroll
    for (int k = 0; k < 2; k++) {
        int c = lane + 32 * k;
        float acc = 0.f;
        #pragma unroll 8
        for (int d = 0; d < CC; d++) acc += scr[warp][d] * sWoT[d * CC + c];
        d_gagg0[row + c] = acc;
    }
}

// ---------------- K9: backward edges -> forces ----------------
__global__ void k_back_edge(const int* __restrict__ eidx,
                            const float* __restrict__ W1, const float* __restrict__ W2,
                            float* __restrict__ force) {
    __shared__ float sW2T[2][CC * CC];   // [i][c*CC+j] = W2[i][j][c]
    __shared__ float sW1p[2][NBAS * 65];
    __shared__ float sA[8][CC];
    __shared__ float sB[8][CC];
    for (int i = threadIdx.x; i < 2 * CC * CC; i += blockDim.x) {
        int w = i / (CC * CC), rem = i % (CC * CC);
        int c = rem / CC, j = rem % CC;
        sW2T[w][rem] = W2[w * CC * CC + j * CC + c];
    }
    for (int i = threadIdx.x; i < 2 * NBAS * CC; i += blockDim.x) {
        int w = i / (NBAS * CC), rem = i % (NBAS * CC);
        int n = rem / CC, j = rem % CC;
        sW1p[w][n * 65 + j] = W1[i];
    }
    __syncthreads();
    int warp = threadIdx.x >> 5, lane = threadIdx.x & 31;
    int e = blockIdx.x * 8 + warp;
    if (e >= EEDGE) return;
    int snd = eidx[e], rcv = eidx[EEDGE + e];
    float Yv[9];
    #pragma unroll
    for (int l = 0; l < 9; l++) Yv[l] = d_Y[e * NL + l];
    float r = d_r[e];
    float ux = d_u3[e * 3], uy = d_u3[e * 3 + 1], uz = d_u3[e * 3 + 2];
    float ef[NBAS];
    #pragma unroll
    for (int n = 0; n < NBAS; n++) ef[n] = d_ef[e * NBAS + n];
    float gs1[2], gR1[2], s0[2], p0[2], t0[2] = {0.f, 0.f};
    #pragma unroll
    for (int k = 0; k < 2; k++) {
        int c = lane + 32 * k;
        float g = d_gagg1[rcv * CC + c];
        gs1[k] = d_R1[e * CC + c] * g;
        gR1[k] = d_s1[e * CC + c] * g;
        s0[k] = d_hu0[snd * CC + c];
        p0[k] = d_R0[e * CC + c] * s0[k];
    }
    float gY[9];
    #pragma unroll
    for (int l = 0; l < 9; l++) {
        float part = 0.f;
        #pragma unroll
        for (int k = 0; k < 2; k++) {
            int c = lane + 32 * k;
            float g0 = d_gagg0[(rcv * NL + l) * CC + c];
            t0[k] += Yv[l] * g0;
            part += p0[k] * g0 + d_hu1[(snd * NL + l) * CC + c] * gs1[k];
        }
        #pragma unroll
        for (int off = 16; off > 0; off >>= 1) part += __shfl_xor_sync(0xffffffff, part, off);
        gY[l] = part;
    }
    float gR0[2] = {t0[0] * s0[0], t0[1] * s0[1]};
    float gef = 0.f;
    #pragma unroll
    for (int i = 0; i < 2; i++) {
        sA[warp][lane] = i ? gR1[0] : gR0[0];
        sA[warp][lane + 32] = i ? gR1[1] : gR0[1];
        __syncwarp();
        #pragma unroll
        for (int k = 0; k < 2; k++) {
            int j = lane + 32 * k;
            float gz = 0.f;
            #pragma unroll 8
            for (int c = 0; c < CC; c++) gz += sA[warp][c] * sW2T[i][c * CC + j];
            float pre = 0.f;
            #pragma unroll
            for (int n = 0; n < NBAS; n++) pre += ef[n] * sW1p[i][n * 65 + j];
            float sg = 1.f / (1.f + __expf(-pre));
            sB[warp][j] = gz * sg * (1.f + pre * (1.f - sg));
        }
        __syncwarp();
        if (lane < NBAS) {
            float acc = 0.f;
            #pragma unroll 8
            for (int j = 0; j < CC; j++) acc += sB[warp][j] * sW1p[i][lane * 65 + j];
            gef += acc;
        }
        __syncwarp();
    }
    float grp = 0.f;
    if (lane < NBAS) {
        float kn = (lane + 1) * (PI_F / RMAXF);
        float inv = 1.f / r;
        const float A = 0.6324555320336759f;
        float sn = sinf(kn * r), cs = cosf(kn * r);
        float uu = r * (1.0f / RMAXF);
        float fc = 0.f, dfc = 0.f;
        if (uu < 1.f) {
            float u2 = uu * uu, u4 = u2 * u2, u5 = u4 * uu, u6 = u5 * uu, u7 = u6 * uu, u8 = u7 * uu;
            fc = 1.f - 28.f * u6 + 48.f * u7 - 21.f * u8;
            dfc = (-168.f * u5 + 336.f * u6 - 168.f * u7) * (1.0f / RMAXF);
        }
        float rb = A * sn * inv;
        float drb = A * (kn * cs - sn * inv) * inv;
        grp = gef * (drb * fc + rb * dfc);
    }
    #pragma unroll
    for (int off = 16; off > 0; off >>= 1) grp += __shfl_xor_sync(0xffffffff, grp, off);
    const float S3 = 1.7320508075688772f, S5 = 2.23606797749979f, S15 = 3.872983346207417f;
    float gux = S3 * gY[1] + S15 * (uy * gY[4] + uz * gY[7] + ux * gY[8]);
    float guy = S3 * gY[2] + S15 * (ux * gY[4] + uz * gY[5] - uy * gY[8]);
    float guz = S3 * gY[3] + S15 * (uy * gY[5] + ux * gY[7]) + 3.f * S5 * uz * gY[6];
    float dot = gux * ux + guy * uy + guz * uz;
    float inv = 1.f / r;
    float gvx = (gux - dot * ux) * inv + grp * ux;
    float gvy = (guy - dot * uy) * inv + grp * uy;
    float gvz = (guz - dot * uz) * inv + grp * uz;
    if (lane == 0 && snd != rcv) {
        atomicAdd(&force[snd * 3 + 0], -gvx);
        atomicAdd(&force[snd * 3 + 1], -gvy);
        atomicAdd(&force[snd * 3 + 2], -gvz);
        atomicAdd(&force[rcv * 3 + 0], gvx);
        atomicAdd(&force[rcv * 3 + 1], gvy);
        atomicAdd(&force[rcv * 3 + 2], gvz);
    }
}

// ---------------- K10: finalize energies ----------------
__global__ void k_final(float* __restrict__ out) {
    int g = threadIdx.x;
    if (g < GG) {
        float c0 = d_contrib[g * 3 + 0], c1 = d_contrib[g * 3 + 1], c2 = d_contrib[g * 3 + 2];
        out[g] = c0 + c1 + c2;
        out[GG + g * 3 + 0] = c0;
        out[GG + g * 3 + 1] = c1;
        out[GG + g * 3 + 2] = c2;
    }
}

extern "C" void kernel_launch(void* const* d_in, const int* in_sizes, int n_in,
                              void* d_out, int out_size) {
    const float* pos     = (const float*)d_in[0];
    const float* attrs   = (const float*)d_in[1];
    const float* shifts  = (const float*)d_in[2];
    const float* ae      = (const float*)d_in[3];
    const float* W_embed = (const float*)d_in[4];
    const float* W_up    = (const float*)d_in[5];
    const float* W1      = (const float*)d_in[6];
    const float* W2      = (const float*)d_in[7];
    const float* W_out   = (const float*)d_in[8];
    const float* W_skip  = (const float*)d_in[9];
    const float* w_read0 = (const float*)d_in[10];
    const float* W_r1    = (const float*)d_in[11];
    const float* w_r2    = (const float*)d_in[12];
    const int*   eidx    = (const int*)d_in[13];
    const int*   batch   = (const int*)d_in[14];
    float* out = (float*)d_out;

    int zgrid = (NNODE * NL * CC + 255) / 256;
    k_zero<<<zgrid, 256>>>(out, out_size);
    k_node_init<<<(NNODE + 7) / 8, 256>>>(attrs, ae, W_embed, W_up /*W_up[0]*/, batch);
    k_edge_geom<<<(EEDGE + 7) / 8, 256>>>(pos, shifts, eidx, W1, W2);
    k_msg0<<<(EEDGE + 7) / 8, 256>>>(eidx);
    k_node_upd<<<(NNODE * NL + 7) / 8, 256>>>(attrs, W_out /*W_out[0]*/, W_skip /*W_skip[0]*/,
                                              w_read0, W_up + CC * CC /*W_up[1]*/, batch);
    k_msg1<<<(EEDGE + 7) / 8, 256>>>(eidx);
    k_node2<<<(NNODE + 7) / 8, 256>>>(attrs, W_out + CC * CC, W_skip + NEL * CC, W_r1, w_r2, batch);
    k_back_scatter<<<(EEDGE + 7) / 8, 256>>>(eidx);
    k_back_node<<<(NNODE * NL + 7) / 8, 256>>>(W_up + CC * CC, W_out, w_read0);
    k_back_edge<<<(EEDGE + 7) / 8, 256>>>(eidx, W1, W2, out + GG + GG * 3);
    k_final<<<1, 64>>>(out);
}

// round 6
// speedup vs baseline: 2.1631x; 2.1631x over previous
#include <cuda_runtime.h>
#include <math.h>

#define NNODE 20000
#define EEDGE 320000
#define CC 64
#define NBAS 8
#define NEL 4
#define GG 16
#define NL 9
#define HIDN 16
#define RMAXF 5.0f
#define PI_F 3.14159265358979f
#define NBLK 592

// ---------------- device scratch ----------------
__device__ float d_hu0[NNODE * CC];
__device__ float d_Y[EEDGE * NL];
__device__ float d_ef[EEDGE * NBAS];
__device__ float d_u3[EEDGE * 3];
__device__ float d_r[EEDGE];
__device__ float d_R0[EEDGE * CC];
__device__ float d_R1[EEDGE * CC];
__device__ float d_agg0[NNODE * NL * CC];
__device__ float d_hu1[NNODE * NL * CC];
__device__ float d_agg1[NNODE * CC];
__device__ float d_gagg1[NNODE * CC];
__device__ float d_ghu1[NNODE * NL * CC];
__device__ float d_gagg0[NNODE * NL * CC];
__device__ float d_contrib[GG * 3];
// precomputed composites
__device__ float d_Wc[CC * CC];     // Wout0 @ Wup1
__device__ float d_WcT[CC * CC];
__device__ float d_vread[CC];       // Wout0 @ w_read0
__device__ float d_skup[NEL * CC];  // Wskip0 @ Wup1
__device__ float d_skrd[NEL];       // Wskip0 @ w_read0
__device__ float d_E0up[NEL * CC];  // W_embed @ Wup0

// ---------------- K0: zero ----------------
__global__ void k_zero(float* __restrict__ out, int out_size) {
    int idx = blockIdx.x * blockDim.x + threadIdx.x;
    int total = NNODE * NL * CC;
    if (idx < total) { d_agg0[idx] = 0.f; d_ghu1[idx] = 0.f; }
    if (idx < NNODE * CC) d_agg1[idx] = 0.f;
    if (idx < out_size) out[idx] = 0.f;
    if (idx < GG * 3) d_contrib[idx] = 0.f;
}

// ---------------- Kpre: composite weights ----------------
__global__ void k_pre(const float* __restrict__ W_embed, const float* __restrict__ W_up,
                      const float* __restrict__ W_out, const float* __restrict__ W_skip,
                      const float* __restrict__ w_read0) {
    int t = threadIdx.x;
    const float* Wup1 = W_up + CC * CC;
    for (int i = t; i < CC * CC; i += blockDim.x) {
        int c = i >> 6, d = i & 63;
        float acc = 0.f;
        #pragma unroll 8
        for (int k = 0; k < CC; k++) acc += W_out[c * CC + k] * Wup1[k * CC + d];
        d_Wc[i] = acc;
        d_WcT[d * CC + c] = acc;
    }
    for (int i = t; i < CC; i += blockDim.x) {
        float acc = 0.f;
        #pragma unroll 8
        for (int d = 0; d < CC; d++) acc += W_out[i * CC + d] * w_read0[d];
        d_vread[i] = acc;
    }
    for (int i = t; i < NEL * CC; i += blockDim.x) {
        int e = i >> 6, d = i & 63;
        float a = 0.f, b = 0.f;
        #pragma unroll 8
        for (int k = 0; k < CC; k++) {
            a += W_skip[e * CC + k] * Wup1[k * CC + d];
            b += W_embed[e * CC + k] * W_up[k * CC + d];
        }
        d_skup[i] = a;
        d_E0up[i] = b;
    }
    if (t < NEL) {
        float acc = 0.f;
        #pragma unroll 8
        for (int d = 0; d < CC; d++) acc += W_skip[t * CC + d] * w_read0[d];
        d_skrd[t] = acc;
    }
}

// ---------------- K1: node init: hu0 = attrs@E0up, e0 ----------------
__global__ void k_node_init(const float* __restrict__ attrs, const float* __restrict__ ae,
                            const int* __restrict__ batch) {
    __shared__ float sE[NEL * CC];
    for (int i = threadIdx.x; i < NEL * CC; i += blockDim.x) sE[i] = d_E0up[i];
    __syncthreads();
    int warp = threadIdx.x >> 5, lane = threadIdx.x & 31;
    int n = blockIdx.x * 8 + warp;
    if (n >= NNODE) return;
    float a0 = attrs[n * 4 + 0], a1 = attrs[n * 4 + 1], a2 = attrs[n * 4 + 2], a3 = attrs[n * 4 + 3];
    #pragma unroll
    for (int k = 0; k < 2; k++) {
        int d = lane + 32 * k;
        d_hu0[n * CC + d] = a0 * sE[d] + a1 * sE[CC + d] + a2 * sE[2 * CC + d] + a3 * sE[3 * CC + d];
    }
    if (lane == 0) {
        float e0 = a0 * ae[0] + a1 * ae[1] + a2 * ae[2] + a3 * ae[3];
        atomicAdd(&d_contrib[batch[n] * 3 + 0], e0);
    }
}

// ---------------- K2+K3 fused: edge geometry + radial MLPs + scatter m0 ----------------
__global__ void k_edge_fwd(const float* __restrict__ pos, const float* __restrict__ shifts,
                           const int* __restrict__ eidx,
                           const float* __restrict__ W1, const float* __restrict__ W2) {
    __shared__ float sW1[2 * NBAS * CC];
    __shared__ float sW2[2 * CC * CC];
    __shared__ __align__(16) float sact[8][CC];
    for (int i = threadIdx.x; i < 2 * NBAS * CC; i += blockDim.x) sW1[i] = W1[i];
    for (int i = threadIdx.x; i < 2 * CC * CC; i += blockDim.x) sW2[i] = W2[i];
    __syncthreads();
    int warp = threadIdx.x >> 5, lane = threadIdx.x & 31;
    for (int e = blockIdx.x * 8 + warp; e < EEDGE; e += gridDim.x * 8) {
        int snd = eidx[e], rcv = eidx[EEDGE + e];
        float vx = pos[snd * 3 + 0] - pos[rcv * 3 + 0] + shifts[e * 3 + 0];
        float vy = pos[snd * 3 + 1] - pos[rcv * 3 + 1] + shifts[e * 3 + 1];
        float vz = pos[snd * 3 + 2] - pos[rcv * 3 + 2] + shifts[e * 3 + 2];
        float r = sqrtf(vx * vx + vy * vy + vz * vz + 1e-12f);
        float inv = 1.0f / r;
        float x = vx * inv, y = vy * inv, z = vz * inv;
        const float S3 = 1.7320508075688772f, S5 = 2.23606797749979f, S15 = 3.872983346207417f;
        float Yv[9];
        Yv[0] = 1.f; Yv[1] = S3 * x; Yv[2] = S3 * y; Yv[3] = S3 * z;
        Yv[4] = S15 * x * y; Yv[5] = S15 * y * z; Yv[6] = 0.5f * S5 * (3.f * z * z - 1.f);
        Yv[7] = S15 * x * z; Yv[8] = 0.5f * S15 * (x * x - y * y);
        float uu = r * (1.0f / RMAXF);
        float fc = 0.f;
        if (uu < 1.f) {
            float u2 = uu * uu, u4 = u2 * u2, u6 = u4 * u2, u7 = u6 * uu, u8 = u7 * uu;
            fc = 1.f - 28.f * u6 + 48.f * u7 - 21.f * u8;
        }
        const float A = 0.6324555320336759f;
        // sin(n*th) via recurrence from one sincosf
        float th = r * (PI_F / RMAXF);
        float sb, cb;
        sincosf(th, &sb, &cb);
        float pref = A * inv * fc;
        float ef[NBAS];
        float sn = sb, cn = cb;
        ef[0] = pref * sn;
        #pragma unroll
        for (int n = 1; n < NBAS; n++) {
            float s2 = sn * cb + cn * sb;
            float c2 = cn * cb - sn * sb;
            sn = s2; cn = c2;
            ef[n] = pref * sn;
        }
        // coalesced stores via select chains (avoid dynamic reg indexing)
        if (lane < 9) {
            float v = Yv[0];
            if (lane == 1) v = Yv[1]; if (lane == 2) v = Yv[2]; if (lane == 3) v = Yv[3];
            if (lane == 4) v = Yv[4]; if (lane == 5) v = Yv[5]; if (lane == 6) v = Yv[6];
            if (lane == 7) v = Yv[7]; if (lane == 8) v = Yv[8];
            d_Y[e * NL + lane] = v;
        }
        if (lane < 8) {
            float v = ef[0];
            if (lane == 1) v = ef[1]; if (lane == 2) v = ef[2]; if (lane == 3) v = ef[3];
            if (lane == 4) v = ef[4]; if (lane == 5) v = ef[5]; if (lane == 6) v = ef[6];
            if (lane == 7) v = ef[7];
            d_ef[e * NBAS + lane] = v;
        }
        if (lane < 3) d_u3[e * 3 + lane] = (lane == 0 ? x : (lane == 1 ? y : z));
        if (lane == 0) d_r[e] = r;
        float h0a = d_hu0[snd * CC + lane], h0b = d_hu0[snd * CC + lane + 32];
        #pragma unroll
        for (int i = 0; i < 2; i++) {
            const float* w1 = &sW1[i * NBAS * CC];
            float z0 = 0.f, z1 = 0.f;
            #pragma unroll
            for (int n = 0; n < NBAS; n++) {
                z0 += ef[n] * w1[n * CC + lane];
                z1 += ef[n] * w1[n * CC + lane + 32];
            }
            float sg0 = 1.f / (1.f + __expf(-z0));
            float sg1 = 1.f / (1.f + __expf(-z1));
            sact[warp][lane] = z0 * sg0;
            sact[warp][lane + 32] = z1 * sg1;
            __syncwarp();
            const float* w2 = &sW2[i * CC * CC];
            const float4* x4 = (const float4*)sact[warp];
            float acc0 = 0.f, acc1 = 0.f;
            #pragma unroll
            for (int c4 = 0; c4 < 16; c4++) {
                float4 xv = x4[c4];
                const float* w = &w2[(c4 * 4) * CC + lane];
                acc0 += xv.x * w[0] + xv.y * w[CC] + xv.z * w[2 * CC] + xv.w * w[3 * CC];
                acc1 += xv.x * w[32] + xv.y * w[CC + 32] + xv.z * w[2 * CC + 32] + xv.w * w[3 * CC + 32];
            }
            if (i == 0) {
                d_R0[e * CC + lane] = acc0;
                d_R0[e * CC + lane + 32] = acc1;
                float p0 = acc0 * h0a, p1 = acc1 * h0b;
                float* base = &d_agg0[rcv * NL * CC];
                #pragma unroll
                for (int l = 0; l < 9; l++) {
                    atomicAdd(base + l * CC + lane, Yv[l] * p0);
                    atomicAdd(base + l * CC + lane + 32, Yv[l] * p1);
                }
            } else {
                d_R1[e * CC + lane] = acc0;
                d_R1[e * CC + lane + 32] = acc1;
            }
            __syncwarp();
        }
    }
}

// ---------------- K4: node update: hu1 = agg0@Wc (+skip/readout) ----------------
__global__ void k_node_upd(const float* __restrict__ attrs, const int* __restrict__ batch) {
    __shared__ float sWc[CC * CC];
    __shared__ float sku[NEL * CC];
    __shared__ float svr[CC];
    __shared__ float sskrd[NEL];
    __shared__ __align__(16) float scr[8][CC];
    for (int i = threadIdx.x; i < CC * CC; i += blockDim.x) sWc[i] = d_Wc[i];
    for (int i = threadIdx.x; i < NEL * CC; i += blockDim.x) sku[i] = d_skup[i];
    for (int i = threadIdx.x; i < CC; i += blockDim.x) svr[i] = d_vread[i];
    if (threadIdx.x < NEL) sskrd[threadIdx.x] = d_skrd[threadIdx.x];
    __syncthreads();
    int warp = threadIdx.x >> 5, lane = threadIdx.x & 31;
    for (int idx = blockIdx.x * 8 + warp; idx < NNODE * NL; idx += gridDim.x * 8) {
        int n = idx / NL, l = idx - n * NL;
        int row = idx * CC;
        float4* s4 = (float4*)scr[warp];
        if (lane < 16) s4[lane] = ((const float4*)&d_agg0[row])[lane];
        __syncwarp();
        float acc0 = 0.f, acc1 = 0.f;
        if (l == 0) {
            float a0 = attrs[n * 4 + 0], a1 = attrs[n * 4 + 1], a2 = attrs[n * 4 + 2], a3 = attrs[n * 4 + 3];
            acc0 = a0 * sku[lane] + a1 * sku[CC + lane] + a2 * sku[2 * CC + lane] + a3 * sku[3 * CC + lane];
            acc1 = a0 * sku[lane + 32] + a1 * sku[CC + lane + 32] + a2 * sku[2 * CC + lane + 32] + a3 * sku[3 * CC + lane + 32];
            float ep = scr[warp][lane] * svr[lane] + scr[warp][lane + 32] * svr[lane + 32];
            #pragma unroll
            for (int off = 16; off > 0; off >>= 1) ep += __shfl_xor_sync(0xffffffff, ep, off);
            if (lane == 0) {
                ep += a0 * sskrd[0] + a1 * sskrd[1] + a2 * sskrd[2] + a3 * sskrd[3];
                atomicAdd(&d_contrib[batch[n] * 3 + 1], ep);
            }
        }
        const float4* x4 = (const float4*)scr[warp];
        #pragma unroll
        for (int c4 = 0; c4 < 16; c4++) {
            float4 xv = x4[c4];
            const float* w = &sWc[(c4 * 4) * CC + lane];
            acc0 += xv.x * w[0] + xv.y * w[CC] + xv.z * w[2 * CC] + xv.w * w[3 * CC];
            acc1 += xv.x * w[32] + xv.y * w[CC + 32] + xv.z * w[2 * CC + 32] + xv.w * w[3 * CC + 32];
        }
        d_hu1[row + lane] = acc0;
        d_hu1[row + lane + 32] = acc1;
        __syncwarp();
    }
}

// ---------------- K5: forward edge iter1: s1, scatter to agg1 ----------------
__global__ void k_msg1(const int* __restrict__ eidx) {
    int warp = threadIdx.x >> 5, lane = threadIdx.x & 31;
    int e = blockIdx.x * 8 + warp;
    if (e >= EEDGE) return;
    int snd = eidx[e], rcv = eidx[EEDGE + e];
    float Yv[9];
    #pragma unroll
    for (int l = 0; l < 9; l++) Yv[l] = d_Y[e * NL + l];
    #pragma unroll
    for (int k = 0; k < 2; k++) {
        int c = lane + 32 * k;
        float s = 0.f;
        #pragma unroll
        for (int l = 0; l < 9; l++) s += d_hu1[(snd * NL + l) * CC + c] * Yv[l];
        atomicAdd(&d_agg1[rcv * CC + c], d_R1[e * CC + c] * s);
    }
}

// ---------------- K6: node2: h2_0, en1, backward head -> g_agg1 ----------------
__global__ void k_node2(const float* __restrict__ attrs, const float* __restrict__ W_out1,
                        const float* __restrict__ W_skip1, const float* __restrict__ W_r1,
                        const float* __restrict__ w_r2, const int* __restrict__ batch) {
    __shared__ float sWo[CC * CC];
    __shared__ float sWoT[CC * CC];
    __shared__ float sWr[CC * 17];
    __shared__ float sr2[HIDN];
    __shared__ float sSk[NEL * CC];
    __shared__ __align__(16) float scr[8][CC];
    __shared__ float sgz[8][HIDN];
    for (int i = threadIdx.x; i < CC * CC; i += blockDim.x) {
        sWo[i] = W_out1[i];
        int d = i / CC, c = i % CC;
        sWoT[i] = W_out1[c * CC + d];
    }
    for (int i = threadIdx.x; i < CC * HIDN; i += blockDim.x) {
        int c = i / HIDN, h = i % HIDN;
        sWr[c * 17 + h] = W_r1[i];
    }
    for (int i = threadIdx.x; i < HIDN; i += blockDim.x) sr2[i] = w_r2[i];
    for (int i = threadIdx.x; i < NEL * CC; i += blockDim.x) sSk[i] = W_skip1[i];
    __syncthreads();
    int warp = threadIdx.x >> 5, lane = threadIdx.x & 31;
    for (int n = blockIdx.x * 8 + warp; n < NNODE; n += gridDim.x * 8) {
        float4* s4 = (float4*)scr[warp];
        if (lane < 16) s4[lane] = ((const float4*)&d_agg1[n * CC])[lane];
        __syncwarp();
        float a0 = attrs[n * 4 + 0], a1 = attrs[n * 4 + 1], a2 = attrs[n * 4 + 2], a3 = attrs[n * 4 + 3];
        float h2a, h2b;
        {
            float acc0 = a0 * sSk[lane] + a1 * sSk[CC + lane] + a2 * sSk[2 * CC + lane] + a3 * sSk[3 * CC + lane];
            float acc1 = a0 * sSk[lane + 32] + a1 * sSk[CC + lane + 32] + a2 * sSk[2 * CC + lane + 32] + a3 * sSk[3 * CC + lane + 32];
            const float4* x4 = (const float4*)scr[warp];
            #pragma unroll
            for (int c4 = 0; c4 < 16; c4++) {
                float4 xv = x4[c4];
                const float* w = &sWo[(c4 * 4) * CC + lane];
                acc0 += xv.x * w[0] + xv.y * w[CC] + xv.z * w[2 * CC] + xv.w * w[3 * CC];
                acc1 += xv.x * w[32] + xv.y * w[CC + 32] + xv.z * w[2 * CC + 32] + xv.w * w[3 * CC + 32];
            }
            h2a = acc0; h2b = acc1;
        }
        __syncwarp();
        scr[warp][lane] = h2a; scr[warp][lane + 32] = h2b;
        __syncwarp();
        float ep = 0.f;
        if (lane < HIDN) {
            float zv = 0.f;
            #pragma unroll 8
            for (int d = 0; d < CC; d++) zv += scr[warp][d] * sWr[d * 17 + lane];
            float sg = 1.f / (1.f + __expf(-zv));
            ep = zv * sg * sr2[lane];
            sgz[warp][lane] = sg * (1.f + zv * (1.f - sg)) * sr2[lane];
        }
        #pragma unroll
        for (int off = 16; off > 0; off >>= 1) ep += __shfl_xor_sync(0xffffffff, ep, off);
        if (lane == 0) atomicAdd(&d_contrib[batch[n] * 3 + 2], ep);
        __syncwarp();
        float gh2a = 0.f, gh2b = 0.f;
        #pragma unroll
        for (int h = 0; h < HIDN; h++) {
            float g = sgz[warp][h];
            gh2a += g * sWr[lane * 17 + h];
            gh2b += g * sWr[(lane + 32) * 17 + h];
        }
        __syncwarp();
        scr[warp][lane] = gh2a; scr[warp][lane + 32] = gh2b;
        __syncwarp();
        {
            const float4* x4 = (const float4*)scr[warp];
            float acc0 = 0.f, acc1 = 0.f;
            #pragma unroll
            for (int c4 = 0; c4 < 16; c4++) {
                float4 xv = x4[c4];
                const float* w = &sWoT[(c4 * 4) * CC + lane];
                acc0 += xv.x * w[0] + xv.y * w[CC] + xv.z * w[2 * CC] + xv.w * w[3 * CC];
                acc1 += xv.x * w[32] + xv.y * w[CC + 32] + xv.z * w[2 * CC + 32] + xv.w * w[3 * CC + 32];
            }
            d_gagg1[n * CC + lane] = acc0;
            d_gagg1[n * CC + lane + 32] = acc1;
        }
        __syncwarp();
    }
}

// ---------------- K7: backward scatter g_hu1 ----------------
__global__ void k_back_scatter(const int* __restrict__ eidx) {
    int warp = threadIdx.x >> 5, lane = threadIdx.x & 31;
    int e = blockIdx.x * 8 + warp;
    if (e >= EEDGE) return;
    int snd = eidx[e], rcv = eidx[EEDGE + e];
    float Yv[9];
    #pragma unroll
    for (int l = 0; l < 9; l++) Yv[l] = d_Y[e * NL + l];
    #pragma unroll
    for (int k = 0; k < 2; k++) {
        int c = lane + 32 * k;
        float gs1 = d_R1[e * CC + c] * d_gagg1[rcv * CC + c];
        float* base = &d_ghu1[(snd * NL) * CC + c];
        #pragma unroll
        for (int l = 0; l < 9; l++) atomicAdd(base + l * CC, Yv[l] * gs1);
    }
}

// ---------------- K8: backward node: g_agg0 = g_hu1@WcT (+vread at l=0) ----------------
__global__ void k_back_node() {
    __shared__ float sWcT[CC * CC];
    __shared__ float svr[CC];
    __shared__ __align__(16) float scr[8][CC];
    for (int i = threadIdx.x; i < CC * CC; i += blockDim.x) sWcT[i] = d_WcT[i];
    for (int i = threadIdx.x; i < CC; i += blockDim.x) svr[i] = d_vread[i];
    __syncthreads();
    int warp = threadIdx.x >> 5, lane = threadIdx.x & 31;
    for (int idx = blockIdx.x * 8 + warp; idx < NNODE * NL; idx += gridDim.x * 8) {
        int l = idx % NL;
        int row = idx * CC;
        float4* s4 = (float4*)scr[warp];
        if (lane < 16) s4[lane] = ((const float4*)&d_ghu1[row])[lane];
        __syncwarp();
        float acc0 = (l == 0) ? svr[lane] : 0.f;
        float acc1 = (l == 0) ? svr[lane + 32] : 0.f;
        const float4* x4 = (const float4*)scr[warp];
        #pragma unroll
        for (int c4 = 0; c4 < 16; c4++) {
            float4 xv = x4[c4];
            const float* w = &sWcT[(c4 * 4) * CC + lane];
            acc0 += xv.x * w[0] + xv.y * w[CC] + xv.z * w[2 * CC] + xv.w * w[3 * CC];
            acc1 += xv.x * w[32] + xv.y * w[CC + 32] + xv.z * w[2 * CC + 32] + xv.w * w[3 * CC + 32];
        }
        d_gagg0[row + lane] = acc0;
        d_gagg0[row + lane + 32] = acc1;
        __syncwarp();
    }
}

// ---------------- K9: backward edges -> forces ----------------
__global__ void k_back_edge(const int* __restrict__ eidx,
                            const float* __restrict__ W1, const float* __restrict__ W2,
                            float* __restrict__ force) {
    __shared__ float sW2T[2][CC * CC];
    __shared__ float sW1p[2][NBAS * 65];
    __shared__ __align__(16) float sA[8][CC];
    __shared__ float sB[8][CC];
    for (int i = threadIdx.x; i < 2 * CC * CC; i += blockDim.x) {
        int w = i / (CC * CC), rem = i % (CC * CC);
        int c = rem / CC, j = rem % CC;
        sW2T[w][rem] = W2[w * CC * CC + j * CC + c];
    }
    for (int i = threadIdx.x; i < 2 * NBAS * CC; i += blockDim.x) {
        int w = i / (NBAS * CC), rem = i % (NBAS * CC);
        int n = rem / CC, j = rem % CC;
        sW1p[w][n * 65 + j] = W1[i];
    }
    __syncthreads();
    int warp = threadIdx.x >> 5, lane = threadIdx.x & 31;
    for (int e = blockIdx.x * 8 + warp; e < EEDGE; e += gridDim.x * 8) {
        int snd = eidx[e], rcv = eidx[EEDGE + e];
        float Yv[9];
        #pragma unroll
        for (int l = 0; l < 9; l++) Yv[l] = d_Y[e * NL + l];
        float r = d_r[e];
        float ux = d_u3[e * 3], uy = d_u3[e * 3 + 1], uz = d_u3[e * 3 + 2];
        float ef[NBAS];
        #pragma unroll
        for (int n = 0; n < NBAS; n++) ef[n] = d_ef[e * NBAS + n];
        float g0 = d_gagg1[rcv * CC + lane], g1 = d_gagg1[rcv * CC + lane + 32];
        float R1a = d_R1[e * CC + lane], R1b = d_R1[e * CC + lane + 32];
        float gs1a = R1a * g0, gs1b = R1b * g1;
        float s0a = d_hu0[snd * CC + lane], s0b = d_hu0[snd * CC + lane + 32];
        float p0a = d_R0[e * CC + lane] * s0a, p0b = d_R0[e * CC + lane + 32] * s0b;
        float t0a = 0.f, t0b = 0.f;
        float s1a = 0.f, s1b = 0.f;
        float gY[9];
        #pragma unroll
        for (int l = 0; l < 9; l++) {
            float ga = d_gagg0[(rcv * NL + l) * CC + lane];
            float gb = d_gagg0[(rcv * NL + l) * CC + lane + 32];
            float ha = d_hu1[(snd * NL + l) * CC + lane];
            float hb = d_hu1[(snd * NL + l) * CC + lane + 32];
            t0a += Yv[l] * ga;
            t0b += Yv[l] * gb;
            s1a += ha * Yv[l];
            s1b += hb * Yv[l];
            float part = p0a * ga + p0b * gb + ha * gs1a + hb * gs1b;
            #pragma unroll
            for (int off = 16; off > 0; off >>= 1) part += __shfl_xor_sync(0xffffffff, part, off);
            gY[l] = part;
        }
        float gR0a = t0a * s0a, gR0b = t0b * s0b;
        float gR1a = s1a * g0, gR1b = s1b * g1;
        float gef = 0.f;
        #pragma unroll
        for (int i = 0; i < 2; i++) {
            sA[warp][lane] = i ? gR1a : gR0a;
            sA[warp][lane + 32] = i ? gR1b : gR0b;
            __syncwarp();
            const float4* x4 = (const float4*)sA[warp];
            #pragma unroll
            for (int k = 0; k < 2; k++) {
                int j = lane + 32 * k;
                float gz = 0.f;
                #pragma unroll
                for (int c4 = 0; c4 < 16; c4++) {
                    float4 xv = x4[c4];
                    const float* w = &sW2T[i][(c4 * 4) * CC + j];
                    gz += xv.x * w[0] + xv.y * w[CC] + xv.z * w[2 * CC] + xv.w * w[3 * CC];
                }
                float pre = 0.f;
                #pragma unroll
                for (int n = 0; n < NBAS; n++) pre += ef[n] * sW1p[i][n * 65 + j];
                float sg = 1.f / (1.f + __expf(-pre));
                sB[warp][j] = gz * sg * (1.f + pre * (1.f - sg));
            }
            __syncwarp();
            if (lane < NBAS) {
                float acc = 0.f;
                #pragma unroll 8
                for (int j = 0; j < CC; j++) acc += sB[warp][j] * sW1p[i][lane * 65 + j];
                gef += acc;
            }
            __syncwarp();
        }
        float grp = 0.f;
        if (lane < NBAS) {
            float kn = (lane + 1) * (PI_F / RMAXF);
            float inv = 1.f / r;
            const float A = 0.6324555320336759f;
            float sn, cs;
            sincosf(kn * r, &sn, &cs);
            float uu = r * (1.0f / RMAXF);
            float fc = 0.f, dfc = 0.f;
            if (uu < 1.f) {
                float u2 = uu * uu, u4 = u2 * u2, u5 = u4 * uu, u6 = u5 * uu, u7 = u6 * uu;
                fc = 1.f - 28.f * u6 + 48.f * u7 - 21.f * u7 * uu;
                dfc = (-168.f * u5 + 336.f * u6 - 168.f * u7) * (1.0f / RMAXF);
            }
            float rb = A * sn * inv;
            float drb = A * (kn * cs - sn * inv) * inv;
            grp = gef * (drb * fc + rb * dfc);
        }
        #pragma unroll
        for (int off = 16; off > 0; off >>= 1) grp += __shfl_xor_sync(0xffffffff, grp, off);
        const float S3 = 1.7320508075688772f, S5 = 2.23606797749979f, S15 = 3.872983346207417f;
        float gux = S3 * gY[1] + S15 * (uy * gY[4] + uz * gY[7] + ux * gY[8]);
        float guy = S3 * gY[2] + S15 * (ux * gY[4] + uz * gY[5] - uy * gY[8]);
        float guz = S3 * gY[3] + S15 * (uy * gY[5] + ux * gY[7]) + 3.f * S5 * uz * gY[6];
        float dot = gux * ux + guy * uy + guz * uz;
        float inv = 1.f / r;
        float gvx = (gux - dot * ux) * inv + grp * ux;
        float gvy = (guy - dot * uy) * inv + grp * uy;
        float gvz = (guz - dot * uz) * inv + grp * uz;
        if (lane == 0 && snd != rcv) {
            atomicAdd(&force[snd * 3 + 0], -gvx);
            atomicAdd(&force[snd * 3 + 1], -gvy);
            atomicAdd(&force[snd * 3 + 2], -gvz);
            atomicAdd(&force[rcv * 3 + 0], gvx);
            atomicAdd(&force[rcv * 3 + 1], gvy);
            atomicAdd(&force[rcv * 3 + 2], gvz);
        }
    }
}

// ---------------- K10: finalize ----------------
__global__ void k_final(float* __restrict__ out) {
    int g = threadIdx.x;
    if (g < GG) {
        float c0 = d_contrib[g * 3 + 0], c1 = d_contrib[g * 3 + 1], c2 = d_contrib[g * 3 + 2];
        out[g] = c0 + c1 + c2;
        out[GG + g * 3 + 0] = c0;
        out[GG + g * 3 + 1] = c1;
        out[GG + g * 3 + 2] = c2;
    }
}

extern "C" void kernel_launch(void* const* d_in, const int* in_sizes, int n_in,
                              void* d_out, int out_size) {
    const float* pos     = (const float*)d_in[0];
    const float* attrs   = (const float*)d_in[1];
    const float* shifts  = (const float*)d_in[2];
    const float* ae      = (const float*)d_in[3];
    const float* W_embed = (const float*)d_in[4];
    const float* W_up    = (const float*)d_in[5];
    const float* W1      = (const float*)d_in[6];
    const float* W2      = (const float*)d_in[7];
    const float* W_out   = (const float*)d_in[8];
    const float* W_skip  = (const float*)d_in[9];
    const float* w_read0 = (const float*)d_in[10];
    const float* W_r1    = (const float*)d_in[11];
    const float* w_r2    = (const float*)d_in[12];
    const int*   eidx    = (const int*)d_in[13];
    const int*   batch   = (const int*)d_in[14];
    float* out = (float*)d_out;

    int zgrid = (NNODE * NL * CC + 255) / 256;
    k_zero<<<zgrid, 256>>>(out, out_size);
    k_pre<<<1, 256>>>(W_embed, W_up, W_out, W_skip, w_read0);
    k_node_init<<<(NNODE + 7) / 8, 256>>>(attrs, ae, batch);
    k_edge_fwd<<<NBLK, 256>>>(pos, shifts, eidx, W1, W2);
    k_node_upd<<<NBLK, 256>>>(attrs, batch);
    k_msg1<<<(EEDGE + 7) / 8, 256>>>(eidx);
    k_node2<<<NBLK, 256>>>(attrs, W_out + CC * CC, W_skip + NEL * CC, W_r1, w_r2, batch);
    k_back_scatter<<<(EEDGE + 7) / 8, 256>>>(eidx);
    k_back_node<<<NBLK, 256>>>();
    k_back_edge<<<NBLK, 256>>>(eidx, W1, W2, out + GG + GG * 3);
    k_final<<<1, 64>>>(out);
}